// round 8
// baseline (speedup 1.0000x reference)
#include <cuda_runtime.h>
#include <cuda_fp16.h>
#include <cstdint>

#define N_NODES 50000
#define N_EDGES 800000
#define IN_F 128
#define OUT_F 128
#define HEADS 4
#define HEAD_DIM 32

// ---------------- scratch (device globals; no allocation allowed) ----------------
__device__ __half g_q[N_NODES * IN_F];      // fp16 q/k/v (edge gather traffic halved)
__device__ __half g_k[N_NODES * IN_F];
__device__ __half g_v[N_NODES * IN_F];
__device__ float  g_agg[N_NODES * OUT_F];   // NORMALIZED attention output (fp32)
__device__ float  g_wot[OUT_F * OUT_F];     // wo transposed
__device__ int    g_cnt[N_NODES];           // in-degree histogram
__device__ int    g_cur[N_NODES];           // scatter cursors
__device__ int    g_rowptr[N_NODES + 1];    // CSR row pointers (by target)
__device__ int    g_src[N_EDGES];           // src node ids, grouped by target

// packed fp32x2 FMA (Blackwell FFMA2 — only reachable via PTX fma.rn.f32x2)
__device__ __forceinline__ unsigned long long ffma2(unsigned long long a,
                                                    unsigned long long b,
                                                    unsigned long long c) {
    unsigned long long d;
    asm("fma.rn.f32x2 %0, %1, %2, %3;" : "=l"(d) : "l"(a), "l"(b), "l"(c));
    return d;
}
__device__ __forceinline__ unsigned long long dup2(float w) {
    unsigned long long d;
    asm("mov.b64 %0, {%1, %1};" : "=l"(d) : "r"(__float_as_uint(w)));
    return d;
}
__device__ __forceinline__ float lo2(unsigned long long p) {
    unsigned int a, b;
    asm("mov.b64 {%0, %1}, %2;" : "=r"(a), "=r"(b) : "l"(p));
    return __uint_as_float(a);
}
__device__ __forceinline__ float hi2(unsigned long long p) {
    unsigned int a, b;
    asm("mov.b64 {%0, %1}, %2;" : "=r"(a), "=r"(b) : "l"(p));
    return __uint_as_float(b);
}

// ---------------- CSR construction ----------------

// zero histogram + transpose wo
__global__ void prep_kernel(const float* __restrict__ wo) {
    int idx = blockIdx.x * blockDim.x + threadIdx.x;
    if (idx < N_NODES) g_cnt[idx] = 0;
    if (idx < OUT_F * OUT_F) {
        int o = idx >> 7, f = idx & 127;
        g_wot[f * OUT_F + o] = wo[idx];
    }
}

__global__ void hist_kernel(const int* __restrict__ ei) {
    int idx = blockIdx.x * blockDim.x + threadIdx.x;
    if (idx < N_EDGES)
        atomicAdd(&g_cnt[ei[N_EDGES + idx]], 1);
}

// single-block exclusive scan of g_cnt -> g_rowptr, g_cur
#define SCAN_T 1024
#define BINS_PER_T 49            // 1024*49 = 50176 >= 50000
__global__ void __launch_bounds__(SCAN_T) scan_kernel() {
    __shared__ int sh[SCAN_T];
    const int th = threadIdx.x;
    const int lo = th * BINS_PER_T;
    int local = 0;
    for (int i = lo; i < lo + BINS_PER_T && i < N_NODES; i++)
        local += g_cnt[i];
    sh[th] = local;
    __syncthreads();
    // Hillis-Steele inclusive scan
    for (int off = 1; off < SCAN_T; off <<= 1) {
        int v = (th >= off) ? sh[th - off] : 0;
        __syncthreads();
        sh[th] += v;
        __syncthreads();
    }
    int run = sh[th] - local;    // exclusive prefix of this thread's chunk
    for (int i = lo; i < lo + BINS_PER_T && i < N_NODES; i++) {
        g_rowptr[i] = run;
        g_cur[i]    = run;
        run += g_cnt[i];
    }
    if (th == 0) g_rowptr[N_NODES] = N_EDGES;
}

__global__ void scatter_kernel(const int* __restrict__ ei) {
    int idx = blockIdx.x * blockDim.x + threadIdx.x;
    if (idx < N_EDGES) {
        int t = ei[N_EDGES + idx];
        int pos = atomicAdd(&g_cur[t], 1);
        g_src[pos] = ei[idx];
    }
}

// ---------------- projections ----------------
#define PROJ_NB 32
#define XS_STRIDE 34
__global__ void __launch_bounds__(128) proj_kernel(
    const float* __restrict__ x,
    const float* __restrict__ wq, const float* __restrict__ bq,
    const float* __restrict__ wk, const float* __restrict__ bk,
    const float* __restrict__ wv, const float* __restrict__ bv)
{
    __shared__ float xs[IN_F * XS_STRIDE];
    const int t = threadIdx.x;
    const int base = blockIdx.x * PROJ_NB;

    for (int k = 0; k < 8; k++) {
        int i = t + k * 128;
        int n = i >> 5, c = i & 31;
        int node = base + n; if (node >= N_NODES) node = N_NODES - 1;
        float4 gx = ((const float4*)(x + (size_t)node * IN_F))[c];
        xs[(4 * c + 0) * XS_STRIDE + n] = gx.x;
        xs[(4 * c + 1) * XS_STRIDE + n] = gx.y;
        xs[(4 * c + 2) * XS_STRIDE + n] = gx.z;
        xs[(4 * c + 3) * XS_STRIDE + n] = gx.w;
    }
    __syncthreads();

    const int h = t >> 5, d = t & 31;
    const float* wqp = wq + h * IN_F * HEAD_DIM + d;
    const float* wkp = wk + h * IN_F * HEAD_DIM + d;
    const float* wvp = wv + h * IN_F * HEAD_DIM + d;

    unsigned long long aq[16], ak[16], av[16];
    const unsigned long long bq2 = dup2(bq[h * HEAD_DIM + d]);
    const unsigned long long bk2 = dup2(bk[h * HEAD_DIM + d]);
    const unsigned long long bv2 = dup2(bv[h * HEAD_DIM + d]);
#pragma unroll
    for (int j = 0; j < 16; j++) { aq[j] = bq2; ak[j] = bk2; av[j] = bv2; }

#pragma unroll 2
    for (int f = 0; f < IN_F; f++) {
        const unsigned long long wq2 = dup2(wqp[f * HEAD_DIM]);
        const unsigned long long wk2 = dup2(wkp[f * HEAD_DIM]);
        const unsigned long long wv2 = dup2(wvp[f * HEAD_DIM]);
        const unsigned long long* xp =
            (const unsigned long long*)(xs + f * XS_STRIDE);
#pragma unroll
        for (int j = 0; j < 16; j++) {
            unsigned long long xpair = xp[j];
            aq[j] = ffma2(xpair, wq2, aq[j]);
            ak[j] = ffma2(xpair, wk2, ak[j]);
            av[j] = ffma2(xpair, wv2, av[j]);
        }
    }

#pragma unroll
    for (int j = 0; j < 16; j++) {
        int n0 = base + 2 * j;
        if (n0 < N_NODES) {
            size_t r = (size_t)n0 * IN_F;
            g_q[r + t] = __float2half_rn(lo2(aq[j]));
            g_k[r + t] = __float2half_rn(lo2(ak[j]));
            g_v[r + t] = __float2half_rn(lo2(av[j]));
        }
        if (n0 + 1 < N_NODES) {
            size_t r = (size_t)(n0 + 1) * IN_F;
            g_q[r + t] = __float2half_rn(hi2(aq[j]));
            g_k[r + t] = __float2half_rn(hi2(ak[j]));
            g_v[r + t] = __float2half_rn(hi2(av[j]));
        }
    }
}

// ---------------- attention aggregation: warp per TARGET node ----------------
// q[t] in registers; loop over CSR src list; ALL accumulation in registers;
// single normalized coalesced store. No atomics, no den array, no agg zeroing.
__device__ __forceinline__ void edge_step(int s, const float2& q0, const float2& q1,
                                          int lane, float& a0, float& a1,
                                          float& a2, float& a3, float& den) {
    const uint2 ka = ((const uint2*)(g_k + (size_t)s * IN_F))[lane];
    float2 k0 = __half22float2(*(const __half2*)&ka.x);
    float2 k1 = __half22float2(*(const __half2*)&ka.y);
    float p = q0.x * k0.x + q0.y * k0.y + q1.x * k1.x + q1.y * k1.y;
    p += __shfl_xor_sync(0xffffffffu, p, 4);
    p += __shfl_xor_sync(0xffffffffu, p, 2);
    p += __shfl_xor_sync(0xffffffffu, p, 1);
    const float ex = __expf(p);
    const uint2 va = ((const uint2*)(g_v + (size_t)s * IN_F))[lane];
    float2 v0 = __half22float2(*(const __half2*)&va.x);
    float2 v1 = __half22float2(*(const __half2*)&va.y);
    a0 += ex * v0.x; a1 += ex * v0.y; a2 += ex * v1.x; a3 += ex * v1.y;
    den += ex;
}

__global__ void __launch_bounds__(256) gat_kernel() {
    const int t = (blockIdx.x * blockDim.x + threadIdx.x) >> 5;   // target node
    const int lane = threadIdx.x & 31;
    if (t >= N_NODES) return;

    const int beg = g_rowptr[t], end = g_rowptr[t + 1];

    const uint2 qa = ((const uint2*)(g_q + (size_t)t * IN_F))[lane];
    const float2 q0 = __half22float2(*(const __half2*)&qa.x);
    const float2 q1 = __half22float2(*(const __half2*)&qa.y);

    float a0 = 0.f, a1 = 0.f, a2 = 0.f, a3 = 0.f, den = 0.f;
    float b0 = 0.f, b1 = 0.f, b2 = 0.f, b3 = 0.f, den2 = 0.f;

    int e = beg;
    for (; e + 1 < end; e += 2) {                  // 2-way unroll for MLP
        const int s0 = __ldg(&g_src[e]);
        const int s1 = __ldg(&g_src[e + 1]);
        edge_step(s0, q0, q1, lane, a0, a1, a2, a3, den);
        edge_step(s1, q0, q1, lane, b0, b1, b2, b3, den2);
    }
    if (e < end)
        edge_step(__ldg(&g_src[e]), q0, q1, lane, a0, a1, a2, a3, den);

    a0 += b0; a1 += b1; a2 += b2; a3 += b3; den += den2;

    const float r = den > 0.f ? __frcp_rn(den) : 0.f;
    float4 o;
    o.x = a0 * r; o.y = a1 * r; o.z = a2 * r; o.w = a3 * r;
    ((float4*)(g_agg + (size_t)t * OUT_F))[lane] = o;
}

// ---------------- output GEMM ----------------
// out = agg @ wo^T + bo (agg already normalized).
#define OUT_NB 32
#define OS_STRIDE 34
__global__ void __launch_bounds__(128) out_kernel(const float* __restrict__ bo,
                                                  float* __restrict__ out)
{
    __shared__ float xs[OUT_F * OS_STRIDE];
    const int t = threadIdx.x;
    const int base = blockIdx.x * OUT_NB;

    for (int k = 0; k < 8; k++) {
        int i = t + k * 128;
        int n = i >> 5, c = i & 31;
        int node = base + n; if (node >= N_NODES) node = N_NODES - 1;
        float4 gx = ((const float4*)(g_agg + (size_t)node * OUT_F))[c];
        xs[(4 * c + 0) * OS_STRIDE + n] = gx.x;
        xs[(4 * c + 1) * OS_STRIDE + n] = gx.y;
        xs[(4 * c + 2) * OS_STRIDE + n] = gx.z;
        xs[(4 * c + 3) * OS_STRIDE + n] = gx.w;
    }
    __syncthreads();

    const int cslot = t & 63;                // columns cslot and cslot+64
    const int mg = t >> 6;                   // node-pair half

    unsigned long long a0[8], a1[8];
    const unsigned long long b0 = dup2(bo[cslot]);
    const unsigned long long b1 = dup2(bo[cslot + 64]);
#pragma unroll
    for (int j = 0; j < 8; j++) { a0[j] = b0; a1[j] = b1; }

#pragma unroll 2
    for (int f = 0; f < OUT_F; f++) {
        const unsigned long long w0 = dup2(g_wot[f * OUT_F + cslot]);
        const unsigned long long w1 = dup2(g_wot[f * OUT_F + cslot + 64]);
        const unsigned long long* xp =
            (const unsigned long long*)(xs + f * OS_STRIDE) + mg * 8;
#pragma unroll
        for (int j = 0; j < 8; j++) {
            unsigned long long xpair = xp[j];
            a0[j] = ffma2(xpair, w0, a0[j]);
            a1[j] = ffma2(xpair, w1, a1[j]);
        }
    }

#pragma unroll
    for (int j = 0; j < 8; j++) {
        int n0 = base + mg * 16 + 2 * j;
        if (n0 < N_NODES) {
            size_t r = (size_t)n0 * OUT_F;
            out[r + cslot]      = lo2(a0[j]);
            out[r + cslot + 64] = lo2(a1[j]);
        }
        if (n0 + 1 < N_NODES) {
            size_t r = (size_t)(n0 + 1) * OUT_F;
            out[r + cslot]      = hi2(a0[j]);
            out[r + cslot + 64] = hi2(a1[j]);
        }
    }
}

// ---------------- launch ----------------
extern "C" void kernel_launch(void* const* d_in, const int* in_sizes, int n_in,
                              void* d_out, int out_size)
{
    const float* x  = (const float*)d_in[0];
    const int*   ei = (const int*)d_in[1];
    const float* wq = (const float*)d_in[2];
    const float* bq = (const float*)d_in[3];
    const float* wk = (const float*)d_in[4];
    const float* bk = (const float*)d_in[5];
    const float* wv = (const float*)d_in[6];
    const float* bv = (const float*)d_in[7];
    const float* wo = (const float*)d_in[8];
    const float* bo = (const float*)d_in[9];
    float* out = (float*)d_out;

    prep_kernel<<<196, 256>>>(wo);                       // 50176 threads
    hist_kernel<<<N_EDGES / 256, 256>>>(ei);
    scan_kernel<<<1, SCAN_T>>>();
    scatter_kernel<<<N_EDGES / 256, 256>>>(ei);
    proj_kernel<<<(N_NODES + PROJ_NB - 1) / PROJ_NB, 128>>>(x, wq, bq, wk, bk, wv, bv);
    gat_kernel<<<(N_NODES + 7) / 8, 256>>>();            // warp per target node
    out_kernel<<<(N_NODES + OUT_NB - 1) / OUT_NB, 128>>>(bo, out);
}

// round 9
// speedup vs baseline: 1.1756x; 1.1756x over previous
#include <cuda_runtime.h>
#include <cuda_fp16.h>
#include <cstdint>

#define N_NODES 50000
#define N_EDGES 800000
#define IN_F 128
#define OUT_F 128
#define HEADS 4
#define HEAD_DIM 32

// ---------------- scratch (device globals; no allocation allowed) ----------------
__device__ __half g_q[N_NODES * IN_F];      // fp16: consumed only by edge gather
__device__ __half g_k[N_NODES * IN_F];
__device__ __half g_v[N_NODES * IN_F];
__device__ float  g_den[N_NODES * HEADS];   // segment sum of exp(score), fp32
__device__ float  g_agg[N_NODES * OUT_F];   // UNNORMALIZED sum of exp(s)*v, fp32

// packed fp32x2 FMA (Blackwell FFMA2 — only reachable via PTX fma.rn.f32x2)
__device__ __forceinline__ unsigned long long ffma2(unsigned long long a,
                                                    unsigned long long b,
                                                    unsigned long long c) {
    unsigned long long d;
    asm("fma.rn.f32x2 %0, %1, %2, %3;" : "=l"(d) : "l"(a), "l"(b), "l"(c));
    return d;
}
__device__ __forceinline__ unsigned long long dup2(float w) {
    unsigned long long d;
    asm("mov.b64 %0, {%1, %1};" : "=l"(d) : "r"(__float_as_uint(w)));
    return d;
}
__device__ __forceinline__ float lo2(unsigned long long p) {
    unsigned int a, b;
    asm("mov.b64 {%0, %1}, %2;" : "=r"(a), "=r"(b) : "l"(p));
    return __uint_as_float(a);
}
__device__ __forceinline__ float hi2(unsigned long long p) {
    unsigned int a, b;
    asm("mov.b64 {%0, %1}, %2;" : "=r"(a), "=r"(b) : "l"(p));
    return __uint_as_float(b);
}

// ---------------- kernels ----------------

// zero agg/den
__global__ void prep_kernel() {
    int idx = blockIdx.x * blockDim.x + threadIdx.x;
    if (idx < N_NODES * OUT_F / 4)
        ((float4*)g_agg)[idx] = make_float4(0.f, 0.f, 0.f, 0.f);
    if (idx < N_NODES * HEADS)
        g_den[idx] = 0.f;
}

// q,k,v projections with node-pair-packed FFMA2 (fp32 math, fp16 stores).
#define PROJ_NB 32
#define XS_STRIDE 34
__global__ void __launch_bounds__(128) proj_kernel(
    const float* __restrict__ x,
    const float* __restrict__ wq, const float* __restrict__ bq,
    const float* __restrict__ wk, const float* __restrict__ bk,
    const float* __restrict__ wv, const float* __restrict__ bv)
{
    __shared__ float xs[IN_F * XS_STRIDE];
    const int t = threadIdx.x;
    const int base = blockIdx.x * PROJ_NB;

    // stage x transposed: xs[f*34 + n] = x[base+n][f]
    for (int k = 0; k < 8; k++) {
        int i = t + k * 128;                 // 0..1023
        int n = i >> 5, c = i & 31;
        int node = base + n; if (node >= N_NODES) node = N_NODES - 1;
        float4 gx = ((const float4*)(x + (size_t)node * IN_F))[c];
        xs[(4 * c + 0) * XS_STRIDE + n] = gx.x;
        xs[(4 * c + 1) * XS_STRIDE + n] = gx.y;
        xs[(4 * c + 2) * XS_STRIDE + n] = gx.z;
        xs[(4 * c + 3) * XS_STRIDE + n] = gx.w;
    }
    __syncthreads();

    const int h = t >> 5, d = t & 31;
    const float* wqp = wq + h * IN_F * HEAD_DIM + d;
    const float* wkp = wk + h * IN_F * HEAD_DIM + d;
    const float* wvp = wv + h * IN_F * HEAD_DIM + d;

    unsigned long long aq[16], ak[16], av[16];
    const unsigned long long bq2 = dup2(bq[h * HEAD_DIM + d]);
    const unsigned long long bk2 = dup2(bk[h * HEAD_DIM + d]);
    const unsigned long long bv2 = dup2(bv[h * HEAD_DIM + d]);
#pragma unroll
    for (int j = 0; j < 16; j++) { aq[j] = bq2; ak[j] = bk2; av[j] = bv2; }

#pragma unroll 2
    for (int f = 0; f < IN_F; f++) {
        const unsigned long long wq2 = dup2(wqp[f * HEAD_DIM]);
        const unsigned long long wk2 = dup2(wkp[f * HEAD_DIM]);
        const unsigned long long wv2 = dup2(wvp[f * HEAD_DIM]);
        const unsigned long long* xp =
            (const unsigned long long*)(xs + f * XS_STRIDE);
#pragma unroll
        for (int j = 0; j < 16; j++) {
            unsigned long long xpair = xp[j];    // nodes 2j, 2j+1 (broadcast LDS.64)
            aq[j] = ffma2(xpair, wq2, aq[j]);
            ak[j] = ffma2(xpair, wk2, ak[j]);
            av[j] = ffma2(xpair, wv2, av[j]);
        }
    }

#pragma unroll
    for (int j = 0; j < 16; j++) {
        int n0 = base + 2 * j;
        if (n0 < N_NODES) {
            size_t r = (size_t)n0 * IN_F;
            g_q[r + t] = __float2half_rn(lo2(aq[j]));
            g_k[r + t] = __float2half_rn(lo2(ak[j]));
            g_v[r + t] = __float2half_rn(lo2(av[j]));
        }
        if (n0 + 1 < N_NODES) {
            size_t r = (size_t)(n0 + 1) * IN_F;
            g_q[r + t] = __float2half_rn(hi2(aq[j]));
            g_k[r + t] = __float2half_rn(hi2(ak[j]));
            g_v[r + t] = __float2half_rn(hi2(av[j]));
        }
    }
}

// FUSED edge pass, 2 edges per warp. fp16 gathers (half traffic), fp32 math/agg.
__global__ void __launch_bounds__(256) edge_kernel(const int* __restrict__ ei) {
    const int w = (blockIdx.x * blockDim.x + threadIdx.x) >> 5;
    const int lane = threadIdx.x & 31;
    const int e0 = w * 2;
    if (e0 >= N_EDGES) return;
    const int e1 = e0 + 1;

    const int s0 = __ldg(&ei[e0]),           s1 = __ldg(&ei[e1]);
    const int t0 = __ldg(&ei[N_EDGES + e0]), t1 = __ldg(&ei[N_EDGES + e1]);

    const uint2 qa0 = ((const uint2*)(g_q + (size_t)t0 * IN_F))[lane];
    const uint2 ka0 = ((const uint2*)(g_k + (size_t)s0 * IN_F))[lane];
    const uint2 qa1 = ((const uint2*)(g_q + (size_t)t1 * IN_F))[lane];
    const uint2 ka1 = ((const uint2*)(g_k + (size_t)s1 * IN_F))[lane];

    float2 qx0 = __half22float2(*(const __half2*)&qa0.x);
    float2 qy0 = __half22float2(*(const __half2*)&qa0.y);
    float2 kx0 = __half22float2(*(const __half2*)&ka0.x);
    float2 ky0 = __half22float2(*(const __half2*)&ka0.y);
    float2 qx1 = __half22float2(*(const __half2*)&qa1.x);
    float2 qy1 = __half22float2(*(const __half2*)&qa1.y);
    float2 kx1 = __half22float2(*(const __half2*)&ka1.x);
    float2 ky1 = __half22float2(*(const __half2*)&ka1.y);

    float p0 = qx0.x * kx0.x + qx0.y * kx0.y + qy0.x * ky0.x + qy0.y * ky0.y;
    float p1 = qx1.x * kx1.x + qx1.y * kx1.y + qy1.x * ky1.x + qy1.y * ky1.y;

    p0 += __shfl_xor_sync(0xffffffffu, p0, 4);
    p1 += __shfl_xor_sync(0xffffffffu, p1, 4);
    p0 += __shfl_xor_sync(0xffffffffu, p0, 2);
    p1 += __shfl_xor_sync(0xffffffffu, p1, 2);
    p0 += __shfl_xor_sync(0xffffffffu, p0, 1);
    p1 += __shfl_xor_sync(0xffffffffu, p1, 1);

    const float ex0 = __expf(p0);
    const float ex1 = __expf(p1);

    const uint2 va0 = ((const uint2*)(g_v + (size_t)s0 * IN_F))[lane];
    const uint2 va1 = ((const uint2*)(g_v + (size_t)s1 * IN_F))[lane];
    float2 vx0 = __half22float2(*(const __half2*)&va0.x);
    float2 vy0 = __half22float2(*(const __half2*)&va0.y);
    float2 vx1 = __half22float2(*(const __half2*)&va1.x);
    float2 vy1 = __half22float2(*(const __half2*)&va1.y);

    float* d0 = g_agg + (size_t)t0 * OUT_F + lane * 4;
    float* d1 = g_agg + (size_t)t1 * OUT_F + lane * 4;
    asm volatile("red.global.add.v4.f32 [%0], {%1, %2, %3, %4};"
                 :: "l"(d0), "f"(ex0 * vx0.x), "f"(ex0 * vx0.y),
                    "f"(ex0 * vy0.x), "f"(ex0 * vy0.y) : "memory");
    asm volatile("red.global.add.v4.f32 [%0], {%1, %2, %3, %4};"
                 :: "l"(d1), "f"(ex1 * vx1.x), "f"(ex1 * vx1.y),
                    "f"(ex1 * vy1.x), "f"(ex1 * vy1.y) : "memory");

    if ((lane & 7) == 0) atomicAdd(&g_den[t0 * HEADS + (lane >> 3)], ex0);
    if ((lane & 7) == 1) atomicAdd(&g_den[t1 * HEADS + (lane >> 3)], ex1);
}

// out = (agg / den) @ wo^T + bo.
// 2 columns per thread; weights read DIRECTLY from wo rows (contiguous per
// thread) as float4 once per 4 f's -> LDG count 8x lower than transposed form.
#define OUT_NB 32
#define OS_STRIDE 34
__global__ void __launch_bounds__(128) out_kernel(const float* __restrict__ wo,
                                                  const float* __restrict__ bo,
                                                  float* __restrict__ out)
{
    __shared__ float xs[OUT_F * OS_STRIDE];
    const int t = threadIdx.x;
    const int base = blockIdx.x * OUT_NB;

    // stage normalized agg transposed: xs[f*34 + n] = agg[base+n][f] / den
    for (int k = 0; k < 8; k++) {
        int i = t + k * 128;                 // 0..1023
        int n = i >> 5, c = i & 31;
        int node = base + n; if (node >= N_NODES) node = N_NODES - 1;
        float den = g_den[node * HEADS + (c >> 3)];
        float r = den > 0.f ? __frcp_rn(den) : 0.f;
        float4 gx = ((const float4*)(g_agg + (size_t)node * OUT_F))[c];
        xs[(4 * c + 0) * OS_STRIDE + n] = gx.x * r;
        xs[(4 * c + 1) * OS_STRIDE + n] = gx.y * r;
        xs[(4 * c + 2) * OS_STRIDE + n] = gx.z * r;
        xs[(4 * c + 3) * OS_STRIDE + n] = gx.w * r;
    }
    __syncthreads();

    const int cslot = t & 63;                // columns cslot and cslot+64
    const int mg = t >> 6;                   // node-pair half: pairs [mg*8, mg*8+8)

    unsigned long long a0[8], a1[8];
    const unsigned long long b0 = dup2(bo[cslot]);
    const unsigned long long b1 = dup2(bo[cslot + 64]);
#pragma unroll
    for (int j = 0; j < 8; j++) { a0[j] = b0; a1[j] = b1; }

    const float4* wr0 = (const float4*)(wo + (size_t)cslot * OUT_F);        // row cslot
    const float4* wr1 = (const float4*)(wo + (size_t)(cslot + 64) * OUT_F); // row cslot+64

#pragma unroll 2
    for (int f4 = 0; f4 < OUT_F / 4; f4++) {
        const float4 w4a = wr0[f4];          // wo[cslot][4f4..4f4+3]   (LDG.128)
        const float4 w4b = wr1[f4];          // wo[cslot+64][4f4..4f4+3]
#pragma unroll
        for (int ff = 0; ff < 4; ff++) {
            const int f = 4 * f4 + ff;
            const unsigned long long w0 =
                dup2(ff == 0 ? w4a.x : ff == 1 ? w4a.y : ff == 2 ? w4a.z : w4a.w);
            const unsigned long long w1 =
                dup2(ff == 0 ? w4b.x : ff == 1 ? w4b.y : ff == 2 ? w4b.z : w4b.w);
            const unsigned long long* xp =
                (const unsigned long long*)(xs + f * OS_STRIDE) + mg * 8;
#pragma unroll
            for (int j = 0; j < 8; j++) {
                unsigned long long xpair = xp[j];   // broadcast LDS.64, reused 2 cols
                a0[j] = ffma2(xpair, w0, a0[j]);
                a1[j] = ffma2(xpair, w1, a1[j]);
            }
        }
    }

#pragma unroll
    for (int j = 0; j < 8; j++) {
        int n0 = base + mg * 16 + 2 * j;
        if (n0 < N_NODES) {
            size_t r = (size_t)n0 * OUT_F;
            out[r + cslot]      = lo2(a0[j]);
            out[r + cslot + 64] = lo2(a1[j]);
        }
        if (n0 + 1 < N_NODES) {
            size_t r = (size_t)(n0 + 1) * OUT_F;
            out[r + cslot]      = hi2(a0[j]);
            out[r + cslot + 64] = hi2(a1[j]);
        }
    }
}

// ---------------- launch ----------------
extern "C" void kernel_launch(void* const* d_in, const int* in_sizes, int n_in,
                              void* d_out, int out_size)
{
    const float* x  = (const float*)d_in[0];
    const int*   ei = (const int*)d_in[1];
    const float* wq = (const float*)d_in[2];
    const float* bq = (const float*)d_in[3];
    const float* wk = (const float*)d_in[4];
    const float* bk = (const float*)d_in[5];
    const float* wv = (const float*)d_in[6];
    const float* bv = (const float*)d_in[7];
    const float* wo = (const float*)d_in[8];
    const float* bo = (const float*)d_in[9];
    float* out = (float*)d_out;

    prep_kernel<<<6250, 256>>>();
    proj_kernel<<<(N_NODES + PROJ_NB - 1) / PROJ_NB, 128>>>(x, wq, bq, wk, bk, wv, bv);
    edge_kernel<<<(N_EDGES / 2 + 7) / 8, 256>>>(ei);   // 2 edges per warp
    out_kernel<<<(N_NODES + OUT_NB - 1) / OUT_NB, 128>>>(wo, bo, out);
}

// round 10
// speedup vs baseline: 1.3001x; 1.1060x over previous
#include <cuda_runtime.h>
#include <cuda_fp16.h>
#include <cstdint>

#define N_NODES 50000
#define N_EDGES 800000
#define IN_F 128
#define OUT_F 128
#define HEADS 4
#define HEAD_DIM 32

// ---------------- scratch (device globals; no allocation allowed) ----------------
__device__ __half g_q[N_NODES * IN_F];      // fp16: consumed only by edge gather
__device__ __half g_k[N_NODES * IN_F];
__device__ __half g_v[N_NODES * IN_F];
__device__ float  g_den[N_NODES * HEADS];   // segment sum of exp(score), fp32
__device__ float  g_agg[N_NODES * OUT_F];   // UNNORMALIZED sum of exp(s)*v, fp32
__device__ float  g_wot[OUT_F * OUT_F];     // wo transposed

// packed fp32x2 FMA (Blackwell FFMA2 — only reachable via PTX fma.rn.f32x2)
__device__ __forceinline__ unsigned long long ffma2(unsigned long long a,
                                                    unsigned long long b,
                                                    unsigned long long c) {
    unsigned long long d;
    asm("fma.rn.f32x2 %0, %1, %2, %3;" : "=l"(d) : "l"(a), "l"(b), "l"(c));
    return d;
}
__device__ __forceinline__ unsigned long long dup2(float w) {
    unsigned long long d;
    asm("mov.b64 %0, {%1, %1};" : "=l"(d) : "r"(__float_as_uint(w)));
    return d;
}
__device__ __forceinline__ float lo2(unsigned long long p) {
    unsigned int a, b;
    asm("mov.b64 {%0, %1}, %2;" : "=r"(a), "=r"(b) : "l"(p));
    return __uint_as_float(a);
}
__device__ __forceinline__ float hi2(unsigned long long p) {
    unsigned int a, b;
    asm("mov.b64 {%0, %1}, %2;" : "=r"(a), "=r"(b) : "l"(p));
    return __uint_as_float(b);
}

// ---------------- kernels ----------------

// zero agg/den + transpose wo
__global__ void prep_kernel(const float* __restrict__ wo) {
    int idx = blockIdx.x * blockDim.x + threadIdx.x;
    if (idx < N_NODES * OUT_F / 4)
        ((float4*)g_agg)[idx] = make_float4(0.f, 0.f, 0.f, 0.f);
    if (idx < N_NODES * HEADS)
        g_den[idx] = 0.f;
    if (idx < OUT_F * OUT_F) {
        int o = idx >> 7, f = idx & 127;
        g_wot[f * OUT_F + o] = wo[idx];
    }
}

// q,k,v projections with node-pair-packed FFMA2 (fp32 math, fp16 stores).
#define PROJ_NB 32
#define XS_STRIDE 34
__global__ void __launch_bounds__(128) proj_kernel(
    const float* __restrict__ x,
    const float* __restrict__ wq, const float* __restrict__ bq,
    const float* __restrict__ wk, const float* __restrict__ bk,
    const float* __restrict__ wv, const float* __restrict__ bv)
{
    __shared__ float xs[IN_F * XS_STRIDE];
    const int t = threadIdx.x;
    const int base = blockIdx.x * PROJ_NB;

    // stage x transposed: xs[f*34 + n] = x[base+n][f]
    for (int k = 0; k < 8; k++) {
        int i = t + k * 128;                 // 0..1023
        int n = i >> 5, c = i & 31;
        int node = base + n; if (node >= N_NODES) node = N_NODES - 1;
        float4 gx = ((const float4*)(x + (size_t)node * IN_F))[c];
        xs[(4 * c + 0) * XS_STRIDE + n] = gx.x;
        xs[(4 * c + 1) * XS_STRIDE + n] = gx.y;
        xs[(4 * c + 2) * XS_STRIDE + n] = gx.z;
        xs[(4 * c + 3) * XS_STRIDE + n] = gx.w;
    }
    __syncthreads();

    const int h = t >> 5, d = t & 31;
    const float* wqp = wq + h * IN_F * HEAD_DIM + d;
    const float* wkp = wk + h * IN_F * HEAD_DIM + d;
    const float* wvp = wv + h * IN_F * HEAD_DIM + d;

    unsigned long long aq[16], ak[16], av[16];
    const unsigned long long bq2 = dup2(bq[h * HEAD_DIM + d]);
    const unsigned long long bk2 = dup2(bk[h * HEAD_DIM + d]);
    const unsigned long long bv2 = dup2(bv[h * HEAD_DIM + d]);
#pragma unroll
    for (int j = 0; j < 16; j++) { aq[j] = bq2; ak[j] = bk2; av[j] = bv2; }

#pragma unroll 2
    for (int f = 0; f < IN_F; f++) {
        const unsigned long long wq2 = dup2(wqp[f * HEAD_DIM]);
        const unsigned long long wk2 = dup2(wkp[f * HEAD_DIM]);
        const unsigned long long wv2 = dup2(wvp[f * HEAD_DIM]);
        const unsigned long long* xp =
            (const unsigned long long*)(xs + f * XS_STRIDE);
#pragma unroll
        for (int j = 0; j < 16; j++) {
            unsigned long long xpair = xp[j];    // nodes 2j, 2j+1 (broadcast LDS.64)
            aq[j] = ffma2(xpair, wq2, aq[j]);
            ak[j] = ffma2(xpair, wk2, ak[j]);
            av[j] = ffma2(xpair, wv2, av[j]);
        }
    }

#pragma unroll
    for (int j = 0; j < 16; j++) {
        int n0 = base + 2 * j;
        if (n0 < N_NODES) {
            size_t r = (size_t)n0 * IN_F;
            g_q[r + t] = __float2half_rn(lo2(aq[j]));
            g_k[r + t] = __float2half_rn(lo2(ak[j]));
            g_v[r + t] = __float2half_rn(lo2(av[j]));
        }
        if (n0 + 1 < N_NODES) {
            size_t r = (size_t)(n0 + 1) * IN_F;
            g_q[r + t] = __float2half_rn(hi2(aq[j]));
            g_k[r + t] = __float2half_rn(hi2(ak[j]));
            g_v[r + t] = __float2half_rn(hi2(av[j]));
        }
    }
}

// FUSED edge pass, 4 edges per warp (doubled MLP vs 2/warp).
// fp16 gathers, fp32 math; red.global.add.v4 for agg; per-head den atomics.
__global__ void __launch_bounds__(256) edge_kernel(const int* __restrict__ ei) {
    const int w = (blockIdx.x * blockDim.x + threadIdx.x) >> 5;
    const int lane = threadIdx.x & 31;
    const int e0 = w * 4;
    if (e0 >= N_EDGES) return;                 // N_EDGES % 4 == 0

    int se[4], te[4];
#pragma unroll
    for (int i = 0; i < 4; i++) {
        se[i] = __ldg(&ei[e0 + i]);
        te[i] = __ldg(&ei[N_EDGES + e0 + i]);
    }

    float p[4];
#pragma unroll
    for (int i = 0; i < 4; i++) {
        const uint2 qa = ((const uint2*)(g_q + (size_t)te[i] * IN_F))[lane];
        const uint2 ka = ((const uint2*)(g_k + (size_t)se[i] * IN_F))[lane];
        float2 q0 = __half22float2(*(const __half2*)&qa.x);
        float2 q1 = __half22float2(*(const __half2*)&qa.y);
        float2 k0 = __half22float2(*(const __half2*)&ka.x);
        float2 k1 = __half22float2(*(const __half2*)&ka.y);
        p[i] = q0.x * k0.x + q0.y * k0.y + q1.x * k1.x + q1.y * k1.y;
    }

#pragma unroll
    for (int off = 4; off > 0; off >>= 1)
#pragma unroll
        for (int i = 0; i < 4; i++)
            p[i] += __shfl_xor_sync(0xffffffffu, p[i], off);

    float ex[4];
#pragma unroll
    for (int i = 0; i < 4; i++) ex[i] = __expf(p[i]);

#pragma unroll
    for (int i = 0; i < 4; i++) {
        const uint2 va = ((const uint2*)(g_v + (size_t)se[i] * IN_F))[lane];
        float2 v0 = __half22float2(*(const __half2*)&va.x);
        float2 v1 = __half22float2(*(const __half2*)&va.y);
        float* dst = g_agg + (size_t)te[i] * OUT_F + lane * 4;
        asm volatile("red.global.add.v4.f32 [%0], {%1, %2, %3, %4};"
                     :: "l"(dst), "f"(ex[i] * v0.x), "f"(ex[i] * v0.y),
                        "f"(ex[i] * v1.x), "f"(ex[i] * v1.y) : "memory");
    }

    // lane = h*8 + i handles den for edge i, head h
    const int i = lane & 7;
    if (i < 4)
        atomicAdd(&g_den[te[i] * HEADS + (lane >> 3)], ex[i]);
}

// out = (agg / den) @ wo^T + bo.
// 2 columns per thread share each x-pair LDS.64 -> LDS:FFMA2 = 1:2.
// 32 nodes/block, 16 ull accs (the 60.4us-measured variant).
#define OUT_NB 32
#define OS_STRIDE 34
__global__ void __launch_bounds__(128) out_kernel(const float* __restrict__ bo,
                                                  float* __restrict__ out)
{
    __shared__ float xs[OUT_F * OS_STRIDE];
    const int t = threadIdx.x;
    const int base = blockIdx.x * OUT_NB;

    // stage normalized agg transposed: xs[f*34 + n] = agg[base+n][f] / den
    for (int k = 0; k < 8; k++) {
        int i = t + k * 128;                 // 0..1023
        int n = i >> 5, c = i & 31;
        int node = base + n; if (node >= N_NODES) node = N_NODES - 1;
        float den = g_den[node * HEADS + (c >> 3)];
        float r = den > 0.f ? __frcp_rn(den) : 0.f;
        float4 gx = ((const float4*)(g_agg + (size_t)node * OUT_F))[c];
        xs[(4 * c + 0) * OS_STRIDE + n] = gx.x * r;
        xs[(4 * c + 1) * OS_STRIDE + n] = gx.y * r;
        xs[(4 * c + 2) * OS_STRIDE + n] = gx.z * r;
        xs[(4 * c + 3) * OS_STRIDE + n] = gx.w * r;
    }
    __syncthreads();

    const int cslot = t & 63;                // columns cslot and cslot+64
    const int mg = t >> 6;                   // node-pair half: pairs [mg*8, mg*8+8)

    unsigned long long a0[8], a1[8];
    const unsigned long long b0 = dup2(bo[cslot]);
    const unsigned long long b1 = dup2(bo[cslot + 64]);
#pragma unroll
    for (int j = 0; j < 8; j++) { a0[j] = b0; a1[j] = b1; }

#pragma unroll 2
    for (int f = 0; f < OUT_F; f++) {
        const unsigned long long w0 = dup2(g_wot[f * OUT_F + cslot]);
        const unsigned long long w1 = dup2(g_wot[f * OUT_F + cslot + 64]);
        const unsigned long long* xp =
            (const unsigned long long*)(xs + f * OS_STRIDE) + mg * 8;
#pragma unroll
        for (int j = 0; j < 8; j++) {
            unsigned long long xpair = xp[j];   // broadcast LDS.64, reused for 2 cols
            a0[j] = ffma2(xpair, w0, a0[j]);
            a1[j] = ffma2(xpair, w1, a1[j]);
        }
    }

#pragma unroll
    for (int j = 0; j < 8; j++) {
        int n0 = base + mg * 16 + 2 * j;
        if (n0 < N_NODES) {
            size_t r = (size_t)n0 * OUT_F;
            out[r + cslot]      = lo2(a0[j]);
            out[r + cslot + 64] = lo2(a1[j]);
        }
        if (n0 + 1 < N_NODES) {
            size_t r = (size_t)(n0 + 1) * OUT_F;
            out[r + cslot]      = hi2(a0[j]);
            out[r + cslot + 64] = hi2(a1[j]);
        }
    }
}

// ---------------- launch ----------------
extern "C" void kernel_launch(void* const* d_in, const int* in_sizes, int n_in,
                              void* d_out, int out_size)
{
    const float* x  = (const float*)d_in[0];
    const int*   ei = (const int*)d_in[1];
    const float* wq = (const float*)d_in[2];
    const float* bq = (const float*)d_in[3];
    const float* wk = (const float*)d_in[4];
    const float* bk = (const float*)d_in[5];
    const float* wv = (const float*)d_in[6];
    const float* bv = (const float*)d_in[7];
    const float* wo = (const float*)d_in[8];
    const float* bo = (const float*)d_in[9];
    float* out = (float*)d_out;

    prep_kernel<<<6250, 256>>>(wo);
    proj_kernel<<<(N_NODES + PROJ_NB - 1) / PROJ_NB, 128>>>(x, wq, bq, wk, bk, wv, bv);
    edge_kernel<<<(N_EDGES / 4) / 8, 256>>>(ei);   // 4 edges per warp
    out_kernel<<<(N_NODES + OUT_NB - 1) / OUT_NB, 128>>>(bo, out);
}